// round 2
// baseline (speedup 1.0000x reference)
#include <cuda_runtime.h>
#include <cuda_bf16.h>
#include <cstdint>

#define NB 16
#define SS 128
#define DK 128
#define NC 100
#define CSZ 8

// ---------------- scratch (device globals; no allocation) ----------------
__device__ float g_AL[NB * SS * DK];            // all_learning [b][s][k]
__device__ float g_P23[(SS - 1) * NB * 256];    // [t][b][0:128]=P2, [128:256]=P3
__device__ float g_P4it[(SS - 1) * NB * DK];
__device__ float g_P5[(SS - 1) * NB * DK];
__device__ float g_W1csum[DK];

// ---------------- helpers ----------------
__device__ __forceinline__ uint32_t smem_u32(const void* p) {
    uint32_t a;
    asm("{ .reg .u64 t; cvta.to.shared.u64 t, %1; cvt.u32.u64 %0, t; }"
        : "=r"(a) : "l"(p));
    return a;
}
__device__ __forceinline__ void cluster_arrive() {
    asm volatile("barrier.cluster.arrive.aligned;" ::: "memory");
}
__device__ __forceinline__ void cluster_wait() {
    asm volatile("barrier.cluster.wait.aligned;" ::: "memory");
}
__device__ __forceinline__ float ld_dsmem(uint32_t addr, uint32_t rank) {
    uint32_t ra;
    asm("mapa.shared::cluster.u32 %0, %1, %2;" : "=r"(ra) : "r"(addr), "r"(rank));
    float v;
    asm volatile("ld.shared::cluster.f32 %0, [%1];" : "=f"(v) : "r"(ra));
    return v;
}
__device__ __forceinline__ float fsig(float x) { return 1.f / (1.f + __expf(-x)); }

// ---------------- precompute kernels ----------------
__global__ void k_w1csum(const float* __restrict__ W1) {
    int k = threadIdx.x;
    float s = 0.f;
    for (int j = 0; j < DK; j++) s += W1[(256 + j) * DK + k];
    g_W1csum[k] = s;
}

// all_learning[b][s][:] = e@W1a + at@W1b + c*colsum(W1c) + b1
__global__ void __launch_bounds__(128) k_al(
    const int* __restrict__ qseq, const int* __restrict__ atseq,
    const float* __restrict__ corr, const float* __restrict__ e_w,
    const float* __restrict__ at_w, const float* __restrict__ W1,
    const float* __restrict__ b1)
{
    __shared__ float ev[8][DK], av[8][DK];
    const int s = blockIdx.x, bg = blockIdx.y, k = threadIdx.x;
    for (int bl = 0; bl < 8; bl++) {
        int bs = (bg * 8 + bl) * SS + s;
        ev[bl][k] = e_w[qseq[bs] * DK + k];
        av[bl][k] = at_w[atseq[bs] * DK + k];
    }
    __syncthreads();
    float acc[8];
    const float cs = g_W1csum[k], bb = b1[k];
    for (int bl = 0; bl < 8; bl++)
        acc[bl] = bb + corr[(bg * 8 + bl) * SS + s] * cs;
    for (int j = 0; j < DK; j++) {
        float we = W1[j * DK + k], wa = W1[(128 + j) * DK + k];
#pragma unroll
        for (int bl = 0; bl < 8; bl++) acc[bl] += ev[bl][j] * we + av[bl][j] * wa;
    }
    for (int bl = 0; bl < 8; bl++)
        g_AL[((bg * 8 + bl) * SS + s) * DK + k] = acc[bl];
}

// P2/P3/P4it/P5 for each step t
__global__ void __launch_bounds__(128) k_pre(
    const int* __restrict__ qseq, const int* __restrict__ itseq,
    const float* __restrict__ e_w, const float* __restrict__ it_w,
    const float* __restrict__ W2, const float* __restrict__ b2,
    const float* __restrict__ W3, const float* __restrict__ b3,
    const float* __restrict__ W4, const float* __restrict__ b4,
    const float* __restrict__ W5, const float* __restrict__ b5)
{
    __shared__ float xp[8][DK], xi[8][DK], xc[8][DK], xe[8][DK];
    const int t = blockIdx.x, bg = blockIdx.y, k = threadIdx.x;
    for (int bl = 0; bl < 8; bl++) {
        int b = bg * 8 + bl;
        xp[bl][k] = (t > 0) ? g_AL[(b * SS + (t - 1)) * DK + k] : 0.f;
        xi[bl][k] = it_w[itseq[b * SS + t] * DK + k];
        xc[bl][k] = g_AL[(b * SS + t) * DK + k];
        xe[bl][k] = e_w[qseq[b * SS + t + 1] * DK + k];
    }
    __syncthreads();
    float a2[8], a3[8];
    {
        float v2 = b2[k], v3 = b3[k];
        for (int bl = 0; bl < 8; bl++) { a2[bl] = v2; a3[bl] = v3; }
    }
    for (int j = 0; j < DK; j++) {
        float w2 = W2[j * DK + k], w3 = W3[j * DK + k];
#pragma unroll
        for (int bl = 0; bl < 8; bl++) { float x = xp[bl][j]; a2[bl] += x * w2; a3[bl] += x * w3; }
    }
    for (int j = 0; j < DK; j++) {
        float w2 = W2[(128 + j) * DK + k], w3 = W3[(128 + j) * DK + k];
#pragma unroll
        for (int bl = 0; bl < 8; bl++) { float x = xi[bl][j]; a2[bl] += x * w2; a3[bl] += x * w3; }
    }
    for (int j = 0; j < DK; j++) {
        float w2 = W2[(256 + j) * DK + k], w3 = W3[(256 + j) * DK + k];
#pragma unroll
        for (int bl = 0; bl < 8; bl++) { float x = xc[bl][j]; a2[bl] += x * w2; a3[bl] += x * w3; }
    }
    for (int bl = 0; bl < 8; bl++) {
        int b = bg * 8 + bl;
        g_P23[(t * NB + b) * 256 + k] = a2[bl];
        g_P23[(t * NB + b) * 256 + 128 + k] = a3[bl];
    }
    float a4[8], a5[8];
    {
        float v4 = b4[k], v5 = b5[k];
        for (int bl = 0; bl < 8; bl++) { a4[bl] = v4; a5[bl] = v5; }
    }
    for (int j = 0; j < DK; j++) {
        float w4 = W4[(256 + j) * DK + k], w5 = W5[j * DK + k];
#pragma unroll
        for (int bl = 0; bl < 8; bl++) { a4[bl] += xi[bl][j] * w4; a5[bl] += xe[bl][j] * w5; }
    }
    for (int bl = 0; bl < 8; bl++) {
        int b = bg * 8 + bl;
        g_P4it[(t * NB + b) * DK + k] = a4[bl];
        g_P5[(t * NB + b) * DK + k] = a5[bl];
    }
}

// ---------------- main sequential kernel ----------------
// smem layout (floats):
#define F_W23DT 0          // [256][132]
#define F_W4HT  33792      // [128][132]
#define F_H     50688      // [13][128]
#define F_PSLOT 52352      // [2][128]  (DSMEM-visible, fixed offset)
#define F_PTBUF 52608      // [2][128]
#define F_HT    52864      // [128]
#define F_LG    52992      // [128]
#define F_ZB    53120      // [256]
#define F_GB    53376      // [2][128]
#define F_QE    53632      // [16]
#define F_QN    53648      // [16]
#define SMEM_FLOATS 53664
#define SMEM_BYTES (SMEM_FLOATS * 4)

__global__ void __cluster_dims__(CSZ, 1, 1) __launch_bounds__(256, 1)
lpkt_main(const int* __restrict__ qseq, const float* __restrict__ qmat,
          const float* __restrict__ h0, const float* __restrict__ W2,
          const float* __restrict__ W3, const float* __restrict__ W4,
          const float* __restrict__ W5, float* __restrict__ out)
{
    extern __shared__ float sm[];
    float* W23dT = sm + F_W23DT;
    float* W4hT  = sm + F_W4HT;
    float* H     = sm + F_H;
    float* PSLOT = sm + F_PSLOT;
    float* PTBUF = sm + F_PTBUF;
    float* HT    = sm + F_HT;
    float* LG    = sm + F_LG;
    float* ZB    = sm + F_ZB;
    float* GB    = sm + F_GB;
    float* QE    = sm + F_QE;
    float* QN    = sm + F_QN;

    const int tid = threadIdx.x;
    const int k = tid & 127;
    const int g = tid >> 7;
    const int batch = blockIdx.x / CSZ;
    const int rank = blockIdx.x % CSZ;
    const int rows = (rank < 4) ? 13 : 12;
    const int n0 = rank * 12 + (rank < 4 ? rank : 4);

    // --- init: stage weights into smem (transposed + padded to 132) ---
    for (int idx = tid; idx < 256 * 128; idx += 256) {
        int col = idx & 255, j = idx >> 8;
        float v = (col < 128) ? W2[(384 + j) * DK + col]
                              : W3[(384 + j) * DK + (col - 128)];
        W23dT[col * 132 + j] = v;
    }
    for (int idx = tid; idx < 128 * 128; idx += 256) {
        int c = idx & 127, j = idx >> 7;
        W4hT[c * 132 + j] = W4[j * DK + c];
    }
    for (int idx = tid; idx < rows * 128; idx += 256)
        H[idx] = h0[n0 * DK + idx];
    {
        int q0 = qseq[batch * SS];
        if (tid < NC) ZB[tid] = qmat[q0 * NC + tid];
    }
    __syncthreads();
    if (g == 0) {  // h_tilde0 = qm[:,0] @ h0 (full, replicated per CTA)
        float acc = 0.f;
        for (int n = 0; n < NC; n++) acc += ZB[n] * h0[n * DK + k];
        HT[k] = acc;
    }
    if (rank == 0 && tid == 0) out[batch * SS] = 0.f;
    __syncthreads();

    const uint32_t pslot_base = smem_u32(PSLOT);

    for (int t = 0; t < SS - 1; t++) {
        // local q-matrix gathers
        if (tid < rows) {
            int qa = qseq[batch * SS + t];
            int qb = qseq[batch * SS + t + 1];
            QE[tid] = qmat[qa * NC + n0 + tid];
            QN[tid] = qmat[qb * NC + n0 + tid];
        }
        // z2/z3 GEMV: 256 output columns
        {
            float acc = g_P23[(t * NB + batch) * 256 + tid];
            const float4* wrow = (const float4*)(W23dT + tid * 132);
            const float4* ht4 = (const float4*)HT;
#pragma unroll
            for (int j4 = 0; j4 < 32; j4++) {
                float4 w = wrow[j4];
                float4 hv = ht4[j4];
                acc += w.x * hv.x + w.y * hv.y + w.z * hv.z + w.w * hv.w;
            }
            ZB[tid] = acc;
        }
        __syncthreads();
        if (g == 0) {
            float a2 = ZB[k], a3 = ZB[128 + k];
            LG[k] = fsig(a3) * (tanhf(a2) + 1.f) * 0.5f;
        }
        __syncthreads();
        // g_vec partials: P4it + LG @ W4[128:256]  (weights via L2)
        {
            float acc = (g == 0) ? g_P4it[(t * NB + batch) * DK + k] : 0.f;
            const int j0 = g * 64;
#pragma unroll 8
            for (int j = 0; j < 64; j++)
                acc += LG[j0 + j] * W4[(128 + j0 + j) * DK + k];
            GB[g * 128 + k] = acc;
        }
        __syncthreads();
        // big GEMM on local h slice + state update + h_tilde partial
        {
            const int ha = (rows + 1) >> 1;
            const int myn0 = g ? ha : 0;
            const int mycnt = g ? (rows - ha) : ha;
            float gval = GB[k] + GB[128 + k];
            float acc[7];
#pragma unroll
            for (int r = 0; r < 7; r++) acc[r] = gval;
            const float4* wrow = (const float4*)(W4hT + k * 132);
#pragma unroll 8
            for (int j4 = 0; j4 < 32; j4++) {
                float4 w = wrow[j4];
#pragma unroll
                for (int r = 0; r < 7; r++) {
                    if (r < mycnt) {
                        float4 hv = *(const float4*)(H + (myn0 + r) * DK + j4 * 4);
                        acc[r] += w.x * hv.x + w.y * hv.y + w.z * hv.z + w.w * hv.w;
                    }
                }
            }
            float hreg[7];
            const float lgk = LG[k];
#pragma unroll
            for (int r = 0; r < 7; r++) {
                if (r < mycnt) {
                    float gamma = fsig(acc[r]);
                    hreg[r] = QE[myn0 + r] * lgk + gamma * H[(myn0 + r) * DK + k];
                }
            }
            __syncthreads();  // all reads of H done before any write
            float pt = 0.f;
#pragma unroll
            for (int r = 0; r < 7; r++) {
                if (r < mycnt) {
                    H[(myn0 + r) * DK + k] = hreg[r];
                    pt += QN[myn0 + r] * hreg[r];
                }
            }
            PTBUF[g * 128 + k] = pt;
        }
        __syncthreads();
        if (tid < 128) PSLOT[(t & 1) * 128 + tid] = PTBUF[tid] + PTBUF[128 + tid];
        cluster_arrive();
        cluster_wait();
        // all-gather h_tilde across the 8 CTA slices via DSMEM
        if (tid < 128) {
            uint32_t addr = pslot_base + (uint32_t)(((t & 1) * 128 + tid) * 4);
            float s = 0.f;
#pragma unroll
            for (int r = 0; r < CSZ; r++) s += ld_dsmem(addr, (uint32_t)r);
            HT[tid] = s;
        }
        __syncthreads();
        // prediction y[t] — round-robin over ranks (uniform branch per CTA)
        if (rank == (t & 7)) {
            float acc = (g == 0) ? g_P5[(t * NB + batch) * DK + k] : 0.f;
            const int j0 = g * 64;
#pragma unroll 8
            for (int j = 0; j < 64; j++)
                acc += HT[j0 + j] * W5[(128 + j0 + j) * DK + k];
            GB[g * 128 + k] = acc;
            __syncthreads();
            if (tid < 128) ZB[tid] = fsig(GB[tid] + GB[128 + tid]);
            __syncthreads();
            if (tid < 32) {
                float s = ZB[tid] + ZB[tid + 32] + ZB[tid + 64] + ZB[tid + 96];
#pragma unroll
                for (int o = 16; o > 0; o >>= 1) s += __shfl_down_sync(0xffffffffu, s, o);
                if (tid == 0) out[batch * SS + t + 1] = s * (1.f / 128.f);
            }
            __syncthreads();
        }
    }
}

// ---------------- launcher ----------------
extern "C" void kernel_launch(void* const* d_in, const int* in_sizes, int n_in,
                              void* d_out, int out_size)
{
    const int* qseq   = (const int*)d_in[0];
    const int* atseq  = (const int*)d_in[1];
    const int* itseq  = (const int*)d_in[2];
    const float* corr = (const float*)d_in[3];
    const float* qmat = (const float*)d_in[4];
    const float* h0   = (const float*)d_in[5];
    const float* e_w  = (const float*)d_in[6];
    const float* at_w = (const float*)d_in[7];
    const float* it_w = (const float*)d_in[8];
    const float* W1 = (const float*)d_in[9];
    const float* b1 = (const float*)d_in[10];
    const float* W2 = (const float*)d_in[11];
    const float* b2 = (const float*)d_in[12];
    const float* W3 = (const float*)d_in[13];
    const float* b3 = (const float*)d_in[14];
    const float* W4 = (const float*)d_in[15];
    const float* b4 = (const float*)d_in[16];
    const float* W5 = (const float*)d_in[17];
    const float* b5 = (const float*)d_in[18];
    float* out = (float*)d_out;

    cudaFuncSetAttribute(lpkt_main, cudaFuncAttributeMaxDynamicSharedMemorySize,
                         SMEM_BYTES);

    k_w1csum<<<1, 128>>>(W1);
    k_al<<<dim3(SS, 2), 128>>>(qseq, atseq, corr, e_w, at_w, W1, b1);
    k_pre<<<dim3(SS - 1, 2), 128>>>(qseq, itseq, e_w, it_w,
                                    W2, b2, W3, b3, W4, b4, W5, b5);
    lpkt_main<<<NB * CSZ, 256, SMEM_BYTES>>>(qseq, qmat, h0, W2, W3, W4, W5, out);
}

// round 3
// speedup vs baseline: 1.5182x; 1.5182x over previous
#include <cuda_runtime.h>
#include <cuda_bf16.h>
#include <cstdint>

#define NB 16
#define SS 128
#define DK 128
#define NC 100
#define CSZ 8
#define RPC 14          // padded rows per CTA (13 real + 1 pad), 7 per half-block

// ---------------- scratch (device globals; no allocation) ----------------
__device__ float g_AL[NB * SS * DK];            // all_learning [b][s][k]
__device__ float g_P23[(SS - 1) * NB * 256];    // [t][b][0:128]=P2, [128:256]=P3
__device__ float g_P4it[(SS - 1) * NB * DK];
__device__ float g_P5[(SS - 1) * NB * DK];
__device__ float g_HT[(SS - 1) * NB * DK];      // h_tilde per step (for pred post-pass)
__device__ float g_W1csum[DK];

// ---------------- helpers ----------------
__device__ __forceinline__ uint32_t smem_u32(const void* p) {
    uint32_t a;
    asm("{ .reg .u64 t; cvta.to.shared.u64 t, %1; cvt.u32.u64 %0, t; }"
        : "=r"(a) : "l"(p));
    return a;
}
__device__ __forceinline__ void cluster_arrive() {
    asm volatile("barrier.cluster.arrive.aligned;" ::: "memory");
}
__device__ __forceinline__ void cluster_wait() {
    asm volatile("barrier.cluster.wait.aligned;" ::: "memory");
}
__device__ __forceinline__ uint32_t mapa_u32(uint32_t addr, uint32_t rank) {
    uint32_t ra;
    asm("mapa.shared::cluster.u32 %0, %1, %2;" : "=r"(ra) : "r"(addr), "r"(rank));
    return ra;
}
__device__ __forceinline__ float ld_dsmem(uint32_t addr) {
    float v;
    asm volatile("ld.shared::cluster.f32 %0, [%1];" : "=f"(v) : "r"(addr));
    return v;
}
__device__ __forceinline__ float fsig(float x) { return 1.f / (1.f + __expf(-x)); }

// ---------------- precompute kernels ----------------
__global__ void k_w1csum(const float* __restrict__ W1) {
    int k = threadIdx.x;
    float s = 0.f;
    for (int j = 0; j < DK; j++) s += W1[(256 + j) * DK + k];
    g_W1csum[k] = s;
}

__global__ void __launch_bounds__(128) k_al(
    const int* __restrict__ qseq, const int* __restrict__ atseq,
    const float* __restrict__ corr, const float* __restrict__ e_w,
    const float* __restrict__ at_w, const float* __restrict__ W1,
    const float* __restrict__ b1)
{
    __shared__ float ev[8][DK], av[8][DK];
    const int s = blockIdx.x, bg = blockIdx.y, k = threadIdx.x;
    for (int bl = 0; bl < 8; bl++) {
        int bs = (bg * 8 + bl) * SS + s;
        ev[bl][k] = e_w[qseq[bs] * DK + k];
        av[bl][k] = at_w[atseq[bs] * DK + k];
    }
    __syncthreads();
    float acc[8];
    const float cs = g_W1csum[k], bb = b1[k];
    for (int bl = 0; bl < 8; bl++)
        acc[bl] = bb + corr[(bg * 8 + bl) * SS + s] * cs;
    for (int j = 0; j < DK; j++) {
        float we = W1[j * DK + k], wa = W1[(128 + j) * DK + k];
#pragma unroll
        for (int bl = 0; bl < 8; bl++) acc[bl] += ev[bl][j] * we + av[bl][j] * wa;
    }
    for (int bl = 0; bl < 8; bl++)
        g_AL[((bg * 8 + bl) * SS + s) * DK + k] = acc[bl];
}

__global__ void __launch_bounds__(128) k_pre(
    const int* __restrict__ qseq, const int* __restrict__ itseq,
    const float* __restrict__ e_w, const float* __restrict__ it_w,
    const float* __restrict__ W2, const float* __restrict__ b2,
    const float* __restrict__ W3, const float* __restrict__ b3,
    const float* __restrict__ W4, const float* __restrict__ b4,
    const float* __restrict__ W5, const float* __restrict__ b5)
{
    __shared__ float xp[8][DK], xi[8][DK], xc[8][DK], xe[8][DK];
    const int t = blockIdx.x, bg = blockIdx.y, k = threadIdx.x;
    for (int bl = 0; bl < 8; bl++) {
        int b = bg * 8 + bl;
        xp[bl][k] = (t > 0) ? g_AL[(b * SS + (t - 1)) * DK + k] : 0.f;
        xi[bl][k] = it_w[itseq[b * SS + t] * DK + k];
        xc[bl][k] = g_AL[(b * SS + t) * DK + k];
        xe[bl][k] = e_w[qseq[b * SS + t + 1] * DK + k];
    }
    __syncthreads();
    float a2[8], a3[8];
    {
        float v2 = b2[k], v3 = b3[k];
        for (int bl = 0; bl < 8; bl++) { a2[bl] = v2; a3[bl] = v3; }
    }
    for (int j = 0; j < DK; j++) {
        float w2 = W2[j * DK + k], w3 = W3[j * DK + k];
#pragma unroll
        for (int bl = 0; bl < 8; bl++) { float x = xp[bl][j]; a2[bl] += x * w2; a3[bl] += x * w3; }
    }
    for (int j = 0; j < DK; j++) {
        float w2 = W2[(128 + j) * DK + k], w3 = W3[(128 + j) * DK + k];
#pragma unroll
        for (int bl = 0; bl < 8; bl++) { float x = xi[bl][j]; a2[bl] += x * w2; a3[bl] += x * w3; }
    }
    for (int j = 0; j < DK; j++) {
        float w2 = W2[(256 + j) * DK + k], w3 = W3[(256 + j) * DK + k];
#pragma unroll
        for (int bl = 0; bl < 8; bl++) { float x = xc[bl][j]; a2[bl] += x * w2; a3[bl] += x * w3; }
    }
    for (int bl = 0; bl < 8; bl++) {
        int b = bg * 8 + bl;
        g_P23[(t * NB + b) * 256 + k] = a2[bl];
        g_P23[(t * NB + b) * 256 + 128 + k] = a3[bl];
    }
    float a4[8], a5[8];
    {
        float v4 = b4[k], v5 = b5[k];
        for (int bl = 0; bl < 8; bl++) { a4[bl] = v4; a5[bl] = v5; }
    }
    for (int j = 0; j < DK; j++) {
        float w4 = W4[(256 + j) * DK + k], w5 = W5[j * DK + k];
#pragma unroll
        for (int bl = 0; bl < 8; bl++) { a4[bl] += xi[bl][j] * w4; a5[bl] += xe[bl][j] * w5; }
    }
    for (int bl = 0; bl < 8; bl++) {
        int b = bg * 8 + bl;
        g_P4it[(t * NB + b) * DK + k] = a4[bl];
        g_P5[(t * NB + b) * DK + k] = a5[bl];
    }
}

// ---------------- main sequential kernel ----------------
// smem layout (floats):
#define F_W23DT 0          // [256][132]
#define F_W4HT  33792      // [128][132]
#define F_H     50688      // [14][128]
#define F_PSLOT 52480      // [2][128]  (DSMEM-visible, fixed offset)
#define F_PTBUF 52736      // [2][128]
#define F_HT    52992      // [128]
#define F_LG    53120      // [128]
#define F_ZB    53248      // [256]
#define F_GB    53504      // [2][128]
#define F_QE    53760      // [16]
#define F_QN    53776      // [16]
#define SMEM_FLOATS 53792
#define SMEM_BYTES (SMEM_FLOATS * 4)

__global__ void __cluster_dims__(CSZ, 1, 1) __launch_bounds__(256, 1)
lpkt_main(const int* __restrict__ qseq, const float* __restrict__ qmat,
          const float* __restrict__ h0, const float* __restrict__ W2,
          const float* __restrict__ W3, const float* __restrict__ W4,
          float* __restrict__ out)
{
    extern __shared__ float sm[];
    float* W23dT = sm + F_W23DT;
    float* W4hT  = sm + F_W4HT;
    float* H     = sm + F_H;
    float* PSLOT = sm + F_PSLOT;
    float* PTBUF = sm + F_PTBUF;
    float* HT    = sm + F_HT;
    float* LG    = sm + F_LG;
    float* ZB    = sm + F_ZB;
    float* GB    = sm + F_GB;
    float* QE    = sm + F_QE;
    float* QN    = sm + F_QN;

    const int tid = threadIdx.x;
    const int k = tid & 127;
    const int g = tid >> 7;
    const int batch = blockIdx.x / CSZ;
    const int rank = blockIdx.x % CSZ;
    const int n0 = rank * 13;           // 13 real rows per CTA (NC padded to 104)
    const int r0 = g * 7;               // each half-block owns 7 of the 14 padded rows

    // --- init: stage weights into smem (transposed + padded to 132) ---
    for (int idx = tid; idx < 256 * 128; idx += 256) {
        int col = idx & 255, j = idx >> 8;
        float v = (col < 128) ? W2[(384 + j) * DK + col]
                              : W3[(384 + j) * DK + (col - 128)];
        W23dT[col * 132 + j] = v;
    }
    for (int idx = tid; idx < 128 * 128; idx += 256) {
        int c = idx & 127, j = idx >> 7;
        W4hT[c * 132 + j] = W4[j * DK + c];
    }
    for (int idx = tid; idx < RPC * 128; idx += 256) {
        int r = idx >> 7, c = idx & 127;
        int n = n0 + r;
        H[idx] = (r < 13 && n < NC) ? h0[n * DK + c] : 0.f;
    }
    {
        int q0 = qseq[batch * SS];
        if (tid < NC) ZB[tid] = qmat[q0 * NC + tid];
    }
    __syncthreads();
    if (g == 0) {  // h_tilde0 = qm[:,0] @ h0 (replicated per CTA), 2 accumulators
        float a0 = 0.f, a1 = 0.f;
        for (int n = 0; n < NC; n += 2) {
            a0 += ZB[n] * h0[n * DK + k];
            a1 += ZB[n + 1] * h0[(n + 1) * DK + k];
        }
        HT[k] = a0 + a1;
    }
    __syncthreads();

    // precompute DSMEM addresses of peers' PSLOT (loop-invariant)
    const uint32_t pslot_base = smem_u32(PSLOT);
    uint32_t raddr[CSZ];
#pragma unroll
    for (int r = 0; r < CSZ; r++) raddr[r] = mapa_u32(pslot_base, (uint32_t)r);

    for (int t = 0; t < SS - 1; t++) {
        // ---- prefetch (fire global loads early) ----
        float p23 = g_P23[(t * NB + batch) * 256 + tid];
        float p4 = (g == 0) ? g_P4it[(t * NB + batch) * DK + k] : 0.f;
        if (tid < RPC) {
            int n = n0 + tid;
            bool valid = (tid < 13) && (n < NC);
            int qa = qseq[batch * SS + t];
            int qb = qseq[batch * SS + t + 1];
            QE[tid] = valid ? qmat[qa * NC + n] : 0.f;
            QN[tid] = valid ? qmat[qb * NC + n] : 0.f;
        }
        // ---- z2/z3 GEMV: 256 outputs, 2 accumulators ----
        {
            float a0 = 0.f, a1 = 0.f;
            const float4* wrow = (const float4*)(W23dT + tid * 132);
            const float4* ht4 = (const float4*)HT;
#pragma unroll
            for (int j4 = 0; j4 < 32; j4 += 2) {
                float4 w0 = wrow[j4], h0v = ht4[j4];
                float4 w1 = wrow[j4 + 1], h1v = ht4[j4 + 1];
                a0 += w0.x * h0v.x + w0.y * h0v.y + w0.z * h0v.z + w0.w * h0v.w;
                a1 += w1.x * h1v.x + w1.y * h1v.y + w1.z * h1v.z + w1.w * h1v.w;
            }
            ZB[tid] = p23 + a0 + a1;
        }
        __syncthreads();
        // (tanh(z2)+1)/2 == sigmoid(2*z2)
        if (g == 0) LG[k] = fsig(ZB[128 + k]) * fsig(2.f * ZB[k]);
        __syncthreads();
        // ---- g partials: P4it + LG @ W4[128:256]  (weights via L2, 4 accumulators) ----
        {
            const int j0 = g * 64;
            const float* w4p = W4 + (128 + j0) * DK + k;
            float b0 = 0.f, b1 = 0.f, b2 = 0.f, b3 = 0.f;
#pragma unroll
            for (int j = 0; j < 64; j += 4) {
                b0 += LG[j0 + j]     * w4p[j * DK];
                b1 += LG[j0 + j + 1] * w4p[(j + 1) * DK];
                b2 += LG[j0 + j + 2] * w4p[(j + 2) * DK];
                b3 += LG[j0 + j + 3] * w4p[(j + 3) * DK];
            }
            GB[g * 128 + k] = p4 + (b0 + b1) + (b2 + b3);
        }
        __syncthreads();
        // ---- big GEMM on 7 fixed rows (branch-free) + update + h_tilde partial ----
        {
            float gval = GB[k] + GB[128 + k];
            float acc[7];
#pragma unroll
            for (int r = 0; r < 7; r++) acc[r] = gval;
            const float4* wrow = (const float4*)(W4hT + k * 132);
            const float4* h4 = (const float4*)H;
#pragma unroll
            for (int j4 = 0; j4 < 32; j4++) {
                float4 w = wrow[j4];
#pragma unroll
                for (int r = 0; r < 7; r++) {
                    float4 hv = h4[(r0 + r) * 32 + j4];   // smem broadcast
                    acc[r] += w.x * hv.x + w.y * hv.y + w.z * hv.z + w.w * hv.w;
                }
            }
            const float lgk = LG[k];
            float hreg[7];
#pragma unroll
            for (int r = 0; r < 7; r++) {
                float hold = H[(r0 + r) * DK + k];
                hreg[r] = QE[r0 + r] * lgk + fsig(acc[r]) * hold;
            }
            __syncthreads();  // all H reads done before writes
            float pa = 0.f, pb = 0.f;
#pragma unroll
            for (int r = 0; r < 7; r++) {
                H[(r0 + r) * DK + k] = hreg[r];
                if (r & 1) pb += QN[r0 + r] * hreg[r];
                else       pa += QN[r0 + r] * hreg[r];
            }
            PTBUF[g * 128 + k] = pa + pb;
        }
        __syncthreads();
        if (tid < 128) PSLOT[(t & 1) * 128 + tid] = PTBUF[tid] + PTBUF[128 + tid];
        cluster_arrive();
        cluster_wait();
        // ---- all-gather h_tilde: 8 back-to-back remote loads, then tree sum ----
        if (tid < 128) {
            const uint32_t off = (uint32_t)(((t & 1) * 128 + tid) * 4);
            float v0 = ld_dsmem(raddr[0] + off);
            float v1 = ld_dsmem(raddr[1] + off);
            float v2 = ld_dsmem(raddr[2] + off);
            float v3 = ld_dsmem(raddr[3] + off);
            float v4 = ld_dsmem(raddr[4] + off);
            float v5 = ld_dsmem(raddr[5] + off);
            float v6 = ld_dsmem(raddr[6] + off);
            float v7 = ld_dsmem(raddr[7] + off);
            float s = ((v0 + v1) + (v2 + v3)) + ((v4 + v5) + (v6 + v7));
            HT[tid] = s;
            if (rank == 0) g_HT[(t * NB + batch) * DK + tid] = s;  // for pred post-pass
        }
        __syncthreads();
    }
}

// ---------------- prediction post-pass (fully parallel) ----------------
__global__ void __launch_bounds__(128) k_pred(
    const float* __restrict__ W5, float* __restrict__ out)
{
    __shared__ float ht[DK];
    __shared__ float red[DK];
    const int t = blockIdx.x, b = blockIdx.y, k = threadIdx.x;
    ht[k] = g_HT[(t * NB + b) * DK + k];
    float acc0 = g_P5[(t * NB + b) * DK + k];
    float acc1 = 0.f, acc2 = 0.f, acc3 = 0.f;
    __syncthreads();
    const float* w5p = W5 + 128 * DK + k;
#pragma unroll 8
    for (int j = 0; j < DK; j += 4) {
        acc0 += ht[j]     * w5p[j * DK];
        acc1 += ht[j + 1] * w5p[(j + 1) * DK];
        acc2 += ht[j + 2] * w5p[(j + 2) * DK];
        acc3 += ht[j + 3] * w5p[(j + 3) * DK];
    }
    red[k] = fsig((acc0 + acc1) + (acc2 + acc3));
    __syncthreads();
    if (k < 32) {
        float s = red[k] + red[k + 32] + red[k + 64] + red[k + 96];
#pragma unroll
        for (int o = 16; o > 0; o >>= 1) s += __shfl_down_sync(0xffffffffu, s, o);
        if (k == 0) {
            out[b * SS + t + 1] = s * (1.f / 128.f);
            if (t == 0) out[b * SS] = 0.f;
        }
    }
}

// ---------------- launcher ----------------
extern "C" void kernel_launch(void* const* d_in, const int* in_sizes, int n_in,
                              void* d_out, int out_size)
{
    const int* qseq   = (const int*)d_in[0];
    const int* atseq  = (const int*)d_in[1];
    const int* itseq  = (const int*)d_in[2];
    const float* corr = (const float*)d_in[3];
    const float* qmat = (const float*)d_in[4];
    const float* h0   = (const float*)d_in[5];
    const float* e_w  = (const float*)d_in[6];
    const float* at_w = (const float*)d_in[7];
    const float* it_w = (const float*)d_in[8];
    const float* W1 = (const float*)d_in[9];
    const float* b1 = (const float*)d_in[10];
    const float* W2 = (const float*)d_in[11];
    const float* b2 = (const float*)d_in[12];
    const float* W3 = (const float*)d_in[13];
    const float* b3 = (const float*)d_in[14];
    const float* W4 = (const float*)d_in[15];
    const float* b4 = (const float*)d_in[16];
    const float* W5 = (const float*)d_in[17];
    const float* b5 = (const float*)d_in[18];
    float* out = (float*)d_out;

    cudaFuncSetAttribute(lpkt_main, cudaFuncAttributeMaxDynamicSharedMemorySize,
                         SMEM_BYTES);

    k_w1csum<<<1, 128>>>(W1);
    k_al<<<dim3(SS, 2), 128>>>(qseq, atseq, corr, e_w, at_w, W1, b1);
    k_pre<<<dim3(SS - 1, 2), 128>>>(qseq, itseq, e_w, it_w,
                                    W2, b2, W3, b3, W4, b4, W5, b5);
    lpkt_main<<<NB * CSZ, 256, SMEM_BYTES>>>(qseq, qmat, h0, W2, W3, W4, out);
    k_pred<<<dim3(SS - 1, NB), 128>>>(W5, out);
}

// round 4
// speedup vs baseline: 1.6145x; 1.0634x over previous
#include <cuda_runtime.h>
#include <cuda_bf16.h>
#include <cstdint>

#define NB 16
#define SS 128
#define DK 128
#define NC 100
#define CSZ 8
#define RPC 14          // padded rows per CTA (13 real + 1 pad), 7 per half-block

// ---------------- scratch (device globals; no allocation) ----------------
__device__ float g_AL[NB * SS * DK];
__device__ float g_P23[(SS - 1) * NB * 256];
__device__ float g_P4it[(SS - 1) * NB * DK];
__device__ float g_P5[(SS - 1) * NB * DK];
__device__ float g_HT[(SS - 1) * NB * DK];
__device__ float g_W1csum[DK];

// ---------------- helpers ----------------
__device__ __forceinline__ uint32_t smem_u32(const void* p) {
    uint32_t a;
    asm("{ .reg .u64 t; cvta.to.shared.u64 t, %1; cvt.u32.u64 %0, t; }"
        : "=r"(a) : "l"(p));
    return a;
}
__device__ __forceinline__ uint32_t mapa_u32(uint32_t addr, uint32_t rank) {
    uint32_t ra;
    asm("mapa.shared::cluster.u32 %0, %1, %2;" : "=r"(ra) : "r"(addr), "r"(rank));
    return ra;
}
__device__ __forceinline__ void mbar_init(uint32_t mbar, uint32_t cnt) {
    asm volatile("mbarrier.init.shared.b64 [%0], %1;" :: "r"(mbar), "r"(cnt) : "memory");
}
__device__ __forceinline__ void mbar_expect(uint32_t mbar, uint32_t bytes) {
    asm volatile("mbarrier.arrive.expect_tx.shared.b64 _, [%0], %1;"
                 :: "r"(mbar), "r"(bytes) : "memory");
}
__device__ __forceinline__ void mbar_wait(uint32_t mbar, uint32_t parity) {
    asm volatile(
        "{\n\t.reg .pred P;\n"
        "WL%=:\n\t"
        "mbarrier.try_wait.parity.shared.b64 P, [%0], %1;\n\t"
        "@P bra WD%=;\n\t"
        "bra WL%=;\n"
        "WD%=:\n\t}"
        :: "r"(mbar), "r"(parity) : "memory");
}
__device__ __forceinline__ void st_async_f32(uint32_t raddr, float v, uint32_t rmbar) {
    asm volatile(
        "st.async.weak.shared::cluster.mbarrier::complete_tx::bytes.f32 [%0], %1, [%2];"
        :: "r"(raddr), "f"(v), "r"(rmbar) : "memory");
}
__device__ __forceinline__ void cluster_arrive() {
    asm volatile("barrier.cluster.arrive.aligned;" ::: "memory");
}
__device__ __forceinline__ void cluster_wait() {
    asm volatile("barrier.cluster.wait.aligned;" ::: "memory");
}
__device__ __forceinline__ float fsig(float x) { return 1.f / (1.f + __expf(-x)); }

// ---------------- precompute kernels ----------------
__global__ void k_w1csum(const float* __restrict__ W1) {
    int k = threadIdx.x;
    float s = 0.f;
    for (int j = 0; j < DK; j++) s += W1[(256 + j) * DK + k];
    g_W1csum[k] = s;
}

__global__ void __launch_bounds__(128) k_al(
    const int* __restrict__ qseq, const int* __restrict__ atseq,
    const float* __restrict__ corr, const float* __restrict__ e_w,
    const float* __restrict__ at_w, const float* __restrict__ W1,
    const float* __restrict__ b1)
{
    __shared__ float ev[8][DK], av[8][DK];
    const int s = blockIdx.x, bg = blockIdx.y, k = threadIdx.x;
    for (int bl = 0; bl < 8; bl++) {
        int bs = (bg * 8 + bl) * SS + s;
        ev[bl][k] = e_w[qseq[bs] * DK + k];
        av[bl][k] = at_w[atseq[bs] * DK + k];
    }
    __syncthreads();
    float acc[8];
    const float cs = g_W1csum[k], bb = b1[k];
    for (int bl = 0; bl < 8; bl++)
        acc[bl] = bb + corr[(bg * 8 + bl) * SS + s] * cs;
    for (int j = 0; j < DK; j++) {
        float we = W1[j * DK + k], wa = W1[(128 + j) * DK + k];
#pragma unroll
        for (int bl = 0; bl < 8; bl++) acc[bl] += ev[bl][j] * we + av[bl][j] * wa;
    }
    for (int bl = 0; bl < 8; bl++)
        g_AL[((bg * 8 + bl) * SS + s) * DK + k] = acc[bl];
}

__global__ void __launch_bounds__(128) k_pre(
    const int* __restrict__ qseq, const int* __restrict__ itseq,
    const float* __restrict__ e_w, const float* __restrict__ it_w,
    const float* __restrict__ W2, const float* __restrict__ b2,
    const float* __restrict__ W3, const float* __restrict__ b3,
    const float* __restrict__ W4, const float* __restrict__ b4,
    const float* __restrict__ W5, const float* __restrict__ b5)
{
    __shared__ float xp[8][DK], xi[8][DK], xc[8][DK], xe[8][DK];
    const int t = blockIdx.x, bg = blockIdx.y, k = threadIdx.x;
    for (int bl = 0; bl < 8; bl++) {
        int b = bg * 8 + bl;
        xp[bl][k] = (t > 0) ? g_AL[(b * SS + (t - 1)) * DK + k] : 0.f;
        xi[bl][k] = it_w[itseq[b * SS + t] * DK + k];
        xc[bl][k] = g_AL[(b * SS + t) * DK + k];
        xe[bl][k] = e_w[qseq[b * SS + t + 1] * DK + k];
    }
    __syncthreads();
    float a2[8], a3[8];
    {
        float v2 = b2[k], v3 = b3[k];
        for (int bl = 0; bl < 8; bl++) { a2[bl] = v2; a3[bl] = v3; }
    }
    for (int j = 0; j < DK; j++) {
        float w2 = W2[j * DK + k], w3 = W3[j * DK + k];
#pragma unroll
        for (int bl = 0; bl < 8; bl++) { float x = xp[bl][j]; a2[bl] += x * w2; a3[bl] += x * w3; }
    }
    for (int j = 0; j < DK; j++) {
        float w2 = W2[(128 + j) * DK + k], w3 = W3[(128 + j) * DK + k];
#pragma unroll
        for (int bl = 0; bl < 8; bl++) { float x = xi[bl][j]; a2[bl] += x * w2; a3[bl] += x * w3; }
    }
    for (int j = 0; j < DK; j++) {
        float w2 = W2[(256 + j) * DK + k], w3 = W3[(256 + j) * DK + k];
#pragma unroll
        for (int bl = 0; bl < 8; bl++) { float x = xc[bl][j]; a2[bl] += x * w2; a3[bl] += x * w3; }
    }
    for (int bl = 0; bl < 8; bl++) {
        int b = bg * 8 + bl;
        g_P23[(t * NB + b) * 256 + k] = a2[bl];
        g_P23[(t * NB + b) * 256 + 128 + k] = a3[bl];
    }
    float a4[8], a5[8];
    {
        float v4 = b4[k], v5 = b5[k];
        for (int bl = 0; bl < 8; bl++) { a4[bl] = v4; a5[bl] = v5; }
    }
    for (int j = 0; j < DK; j++) {
        float w4 = W4[(256 + j) * DK + k], w5 = W5[j * DK + k];
#pragma unroll
        for (int bl = 0; bl < 8; bl++) { a4[bl] += xi[bl][j] * w4; a5[bl] += xe[bl][j] * w5; }
    }
    for (int bl = 0; bl < 8; bl++) {
        int b = bg * 8 + bl;
        g_P4it[(t * NB + b) * DK + k] = a4[bl];
        g_P5[(t * NB + b) * DK + k] = a5[bl];
    }
}

// ---------------- main sequential kernel ----------------
// smem layout (float offsets):
#define F_MBAR  0          // 2 mbarriers (16 bytes)
#define F_W23DT 4          // [256][132]
#define F_W4HT  33796      // [128][132]
#define F_H     50692      // [14][128]
#define F_SLOT  52484      // [2][128][8]  (DSMEM-visible slots)
#define F_HT    54532      // [128]
#define F_LG    54660      // [128]
#define F_ZB    54788      // [256]
#define F_GB    55044      // [2][128]
#define F_PTBUF 55300      // [2][128]
#define F_QE    55556      // [16]
#define F_QN    55572      // [16]
#define SMEM_FLOATS 55588
#define SMEM_BYTES (SMEM_FLOATS * 4)

__global__ void __cluster_dims__(CSZ, 1, 1) __launch_bounds__(256, 1)
lpkt_main(const int* __restrict__ qseq, const float* __restrict__ qmat,
          const float* __restrict__ h0, const float* __restrict__ W2,
          const float* __restrict__ W3, const float* __restrict__ W4,
          float* __restrict__ out)
{
    extern __shared__ float sm[];
    float* W23dT = sm + F_W23DT;
    float* W4hT  = sm + F_W4HT;
    float* H     = sm + F_H;
    float* SLOT  = sm + F_SLOT;
    float* HT    = sm + F_HT;
    float* LG    = sm + F_LG;
    float* ZB    = sm + F_ZB;
    float* GB    = sm + F_GB;
    float* PTBUF = sm + F_PTBUF;
    float* QE    = sm + F_QE;
    float* QN    = sm + F_QN;

    const int tid = threadIdx.x;
    const int k = tid & 127;
    const int g = tid >> 7;
    const int batch = blockIdx.x / CSZ;
    const int rank = blockIdx.x % CSZ;
    const int n0 = rank * 13;
    const int r0 = g * 7;

    const uint32_t smbase = smem_u32(sm);
    const uint32_t mbar_local = smbase;          // barrier p at smbase + p*8

    // --- mbarrier init (arrival count 1 = the expect_tx arrive) ---
    if (tid == 0) { mbar_init(mbar_local, 1); mbar_init(mbar_local + 8, 1); }

    // --- W4 mid-chunk into registers (loop-invariant) ---
    float w4r[64];
#pragma unroll
    for (int j = 0; j < 64; j++)
        w4r[j] = W4[(128 + g * 64 + j) * DK + k];

    // --- stage weights into smem ---
    for (int idx = tid; idx < 256 * 128; idx += 256) {
        int col = idx & 255, j = idx >> 8;
        float v = (col < 128) ? W2[(384 + j) * DK + col]
                              : W3[(384 + j) * DK + (col - 128)];
        W23dT[col * 132 + j] = v;
    }
    for (int idx = tid; idx < 128 * 128; idx += 256) {
        int c = idx & 127, j = idx >> 7;
        W4hT[c * 132 + j] = W4[j * DK + c];
    }
    for (int idx = tid; idx < RPC * 128; idx += 256) {
        int r = idx >> 7, c = idx & 127;
        int n = n0 + r;
        H[idx] = (r < 13 && n < NC) ? h0[n * DK + c] : 0.f;
    }
    {
        int q0 = qseq[batch * SS];
        if (tid < NC) ZB[tid] = qmat[q0 * NC + tid];
    }
    __syncthreads();
    if (g == 0) {
        float a0 = 0.f, a1 = 0.f;
        for (int n = 0; n < NC; n += 2) {
            a0 += ZB[n] * h0[n * DK + k];
            a1 += ZB[n + 1] * h0[(n + 1) * DK + k];
        }
        HT[k] = a0 + a1;
    }
    __syncthreads();
    cluster_arrive();          // one-time: mbarrier init visible cluster-wide
    cluster_wait();

    // peer smem bases (loop-invariant)
    uint32_t rbase[CSZ];
#pragma unroll
    for (int r = 0; r < CSZ; r++) rbase[r] = mapa_u32(smbase, (uint32_t)r);

    int ph0 = 0, ph1 = 0;

    for (int t = 0; t < SS - 1; t++) {
        const int pn = (t + 1) & 1;
        // expect_tx for NEXT phase's incoming partials (8 srcs x 512B)
        if (tid == 0) mbar_expect(mbar_local + pn * 8, CSZ * 128 * 4);

        // ---- prefetch globals (hidden under GEMM) ----
        float p23 = g_P23[(t * NB + batch) * 256 + tid];
        float p4 = (g == 0) ? g_P4it[(t * NB + batch) * DK + k] : 0.f;
        if (tid < RPC) {
            int n = n0 + tid;
            bool valid = (tid < 13) && (n < NC);
            int qa = qseq[batch * SS + t];
            int qb = qseq[batch * SS + t + 1];
            QE[tid] = valid ? qmat[qa * NC + n] : 0.f;
            QN[tid] = valid ? qmat[qb * NC + n] : 0.f;
        }

        // ---- big GEMM h @ W4h — independent of incoming h_tilde ----
        float acc[7];
#pragma unroll
        for (int r = 0; r < 7; r++) acc[r] = 0.f;
        {
            const float4* wrow = (const float4*)(W4hT + k * 132);
            const float4* h4 = (const float4*)H;
#pragma unroll
            for (int j4 = 0; j4 < 32; j4++) {
                float4 w = wrow[j4];
#pragma unroll
                for (int r = 0; r < 7; r++) {
                    float4 hv = h4[(r0 + r) * 32 + j4];
                    acc[r] += w.x * hv.x + w.y * hv.y + w.z * hv.z + w.w * hv.w;
                }
            }
        }

        // ---- wait for h_tilde partials (t>0), sum 8 slots locally ----
        if (t > 0) {
            const int p = t & 1;
            mbar_wait(mbar_local + p * 8, p ? ph1 : ph0);
            if (p) ph1 ^= 1; else ph0 ^= 1;
            if (tid < 128) {
                const float4* s4 = (const float4*)(SLOT + p * 1024 + tid * 8);
                float4 a = s4[0], b = s4[1];
                float s = ((a.x + a.y) + (a.z + a.w)) + ((b.x + b.y) + (b.z + b.w));
                HT[tid] = s;
                if (rank == 0) g_HT[((t - 1) * NB + batch) * DK + tid] = s;
            }
            __syncthreads();
        }

        // ---- z2/z3 GEMV (4 accumulators) ----
        {
            float a0 = 0.f, a1 = 0.f, a2 = 0.f, a3 = 0.f;
            const float4* wrow = (const float4*)(W23dT + tid * 132);
            const float4* ht4 = (const float4*)HT;
#pragma unroll
            for (int j4 = 0; j4 < 32; j4 += 4) {
                float4 w0 = wrow[j4],     x0 = ht4[j4];
                float4 w1 = wrow[j4 + 1], x1 = ht4[j4 + 1];
                float4 w2 = wrow[j4 + 2], x2 = ht4[j4 + 2];
                float4 w3 = wrow[j4 + 3], x3 = ht4[j4 + 3];
                a0 += w0.x * x0.x + w0.y * x0.y + w0.z * x0.z + w0.w * x0.w;
                a1 += w1.x * x1.x + w1.y * x1.y + w1.z * x1.z + w1.w * x1.w;
                a2 += w2.x * x2.x + w2.y * x2.y + w2.z * x2.z + w2.w * x2.w;
                a3 += w3.x * x3.x + w3.y * x3.y + w3.z * x3.z + w3.w * x3.w;
            }
            ZB[tid] = p23 + (a0 + a1) + (a2 + a3);
        }
        __syncthreads();
        // LG = sigmoid(z3) * sigmoid(2*z2)
        float lgk = fsig(ZB[128 + k]) * fsig(2.f * ZB[k]);
        if (g == 0) LG[k] = lgk;
        __syncthreads();

        // ---- g partials from register-resident W4 mid-chunk ----
        {
            float b0 = 0.f, b1 = 0.f, b2 = 0.f, b3 = 0.f;
            const float* lgp = LG + g * 64;
#pragma unroll
            for (int j = 0; j < 64; j += 4) {
                b0 += w4r[j]     * lgp[j];
                b1 += w4r[j + 1] * lgp[j + 1];
                b2 += w4r[j + 2] * lgp[j + 2];
                b3 += w4r[j + 3] * lgp[j + 3];
            }
            GB[tid] = p4 + (b0 + b1) + (b2 + b3);
        }
        __syncthreads();

        // ---- finish gamma, update H, partial h_tilde ----
        {
            float gval = GB[k] + GB[128 + k];
            float pa = 0.f, pb = 0.f;
#pragma unroll
            for (int r = 0; r < 7; r++) {
                float hold = H[(r0 + r) * DK + k];
                float hnew = QE[r0 + r] * lgk + fsig(acc[r] + gval) * hold;
                H[(r0 + r) * DK + k] = hnew;
                if (r & 1) pb += QN[r0 + r] * hnew;
                else       pa += QN[r0 + r] * hnew;
            }
            PTBUF[tid] = pa + pb;
        }
        __syncthreads();

        // ---- push combined partial to all 8 peers (incl. self) ----
        if (tid < 128) {
            float c = PTBUF[tid] + PTBUF[128 + tid];
            const uint32_t soff = (uint32_t)((F_SLOT + pn * 1024 + tid * 8 + rank) * 4);
#pragma unroll
            for (int r = 0; r < CSZ; r++)
                st_async_f32(rbase[r] + soff, c, rbase[r] + (uint32_t)(pn * 8));
        }
    }

    // ---- final exchange: h_tilde after last update (t index 126) ----
    {
        mbar_wait(mbar_local + 8, ph1);
        if (rank == 0 && tid < 128) {
            const float4* s4 = (const float4*)(SLOT + 1024 + tid * 8);
            float4 a = s4[0], b = s4[1];
            float s = ((a.x + a.y) + (a.z + a.w)) + ((b.x + b.y) + (b.z + b.w));
            g_HT[(126 * NB + batch) * DK + tid] = s;
        }
    }
}

// ---------------- prediction post-pass (fully parallel) ----------------
__global__ void __launch_bounds__(128) k_pred(
    const float* __restrict__ W5, float* __restrict__ out)
{
    __shared__ float ht[DK];
    __shared__ float red[DK];
    const int t = blockIdx.x, b = blockIdx.y, k = threadIdx.x;
    ht[k] = g_HT[(t * NB + b) * DK + k];
    float acc0 = g_P5[(t * NB + b) * DK + k];
    float acc1 = 0.f, acc2 = 0.f, acc3 = 0.f;
    __syncthreads();
    const float* w5p = W5 + 128 * DK + k;
#pragma unroll 8
    for (int j = 0; j < DK; j += 4) {
        acc0 += ht[j]     * w5p[j * DK];
        acc1 += ht[j + 1] * w5p[(j + 1) * DK];
        acc2 += ht[j + 2] * w5p[(j + 2) * DK];
        acc3 += ht[j + 3] * w5p[(j + 3) * DK];
    }
    red[k] = fsig((acc0 + acc1) + (acc2 + acc3));
    __syncthreads();
    if (k < 32) {
        float s = red[k] + red[k + 32] + red[k + 64] + red[k + 96];
#pragma unroll
        for (int o = 16; o > 0; o >>= 1) s += __shfl_down_sync(0xffffffffu, s, o);
        if (k == 0) {
            out[b * SS + t + 1] = s * (1.f / 128.f);
            if (t == 0) out[b * SS] = 0.f;
        }
    }
}

// ---------------- launcher ----------------
extern "C" void kernel_launch(void* const* d_in, const int* in_sizes, int n_in,
                              void* d_out, int out_size)
{
    const int* qseq   = (const int*)d_in[0];
    const int* atseq  = (const int*)d_in[1];
    const int* itseq  = (const int*)d_in[2];
    const float* corr = (const float*)d_in[3];
    const float* qmat = (const float*)d_in[4];
    const float* h0   = (const float*)d_in[5];
    const float* e_w  = (const float*)d_in[6];
    const float* at_w = (const float*)d_in[7];
    const float* it_w = (const float*)d_in[8];
    const float* W1 = (const float*)d_in[9];
    const float* b1 = (const float*)d_in[10];
    const float* W2 = (const float*)d_in[11];
    const float* b2 = (const float*)d_in[12];
    const float* W3 = (const float*)d_in[13];
    const float* b3 = (const float*)d_in[14];
    const float* W4 = (const float*)d_in[15];
    const float* b4 = (const float*)d_in[16];
    const float* W5 = (const float*)d_in[17];
    const float* b5 = (const float*)d_in[18];
    float* out = (float*)d_out;

    cudaFuncSetAttribute(lpkt_main, cudaFuncAttributeMaxDynamicSharedMemorySize,
                         SMEM_BYTES);

    k_w1csum<<<1, 128>>>(W1);
    k_al<<<dim3(SS, 2), 128>>>(qseq, atseq, corr, e_w, at_w, W1, b1);
    k_pre<<<dim3(SS - 1, 2), 128>>>(qseq, itseq, e_w, it_w,
                                    W2, b2, W3, b3, W4, b4, W5, b5);
    lpkt_main<<<NB * CSZ, 256, SMEM_BYTES>>>(qseq, qmat, h0, W2, W3, W4, out);
    k_pred<<<dim3(SS - 1, NB), 128>>>(W5, out);
}